// round 4
// baseline (speedup 1.0000x reference)
#include <cuda_runtime.h>
#include <math.h>

// Problem constants
#define Nn   131072
#define Ee   1048576
#define Bb   1024
#define FIN  128
#define HID  128
#define DD   384
#define KK   30
#define C1n  16
#define C2n  32
#define KERNL 5
#define L2n  26
#define PL   13
#define FLAT 416
#define EPSc 1e-5f
#define SMAX 2048
#define SCANB 512

// packed fp32x2 helpers
#define UNPACKF2(lo, hi, in) \
    { unsigned int _a, _b; asm("mov.b64 {%0, %1}, %2;" : "=r"(_a), "=r"(_b) : "l"(in)); \
      lo = __uint_as_float(_a); hi = __uint_as_float(_b); }
#define FMAF2(acc, a, b) \
    asm("fma.rn.f32x2 %0, %1, %2, %0;" : "+l"(acc) : "l"(a), "l"(b))

// ---------------- scratch ----------------------------------------------------
__device__ float g_dis[Nn];
__device__ int   g_cnt[Nn];
__device__ int   g_offs[Nn + 1];
__device__ int   g_cursor[Nn];
__device__ int   g_csr[Ee];
__device__ float g_Agg[(size_t)Nn * HID];
__device__ float g_Y[(size_t)Nn * HID];
__device__ float g_X[(size_t)Nn * DD];
__device__ int   g_bcnt[Bb];
__device__ int   g_starts[Bb];
__device__ int   g_bsum[SCANB];
__device__ int   g_bbase[SCANB];

// ---------------- init -------------------------------------------------------
__global__ void init_kernel() {
    int i = blockIdx.x * blockDim.x + threadIdx.x;
    if (i < Nn) g_cnt[i] = 0;
    if (i < Bb) g_bcnt[i] = 0;
}

__global__ void count_kernel(const int* __restrict__ col, const int* __restrict__ batch) {
    int e = blockIdx.x * blockDim.x + threadIdx.x;
    if (e < Ee) atomicAdd(&g_cnt[col[e]], 1);
    if (e < Nn) atomicAdd(&g_bcnt[batch[e]], 1);
}

// ---------------- hierarchical scan over node counts ------------------------
__global__ void scanA_kernel() {
    __shared__ int s[256];
    int tid = threadIdx.x;
    int i = blockIdx.x * 256 + tid;
    int c = g_cnt[i];
    s[tid] = c;
    __syncthreads();
    #pragma unroll
    for (int off = 1; off < 256; off <<= 1) {
        int v = (tid >= off) ? s[tid - off] : 0;
        __syncthreads();
        s[tid] += v;
        __syncthreads();
    }
    g_offs[i] = s[tid] - c;
    if (tid == 255) g_bsum[blockIdx.x] = s[255];
}

__global__ void scanB_kernel() {
    __shared__ int s[SCANB];
    int tid = threadIdx.x;
    int c = g_bsum[tid];
    s[tid] = c;
    __syncthreads();
    for (int off = 1; off < SCANB; off <<= 1) {
        int v = (tid >= off) ? s[tid - off] : 0;
        __syncthreads();
        s[tid] += v;
        __syncthreads();
    }
    g_bbase[tid] = s[tid] - c;
}

__global__ void scanC_kernel() {
    int tid = threadIdx.x;
    int i = blockIdx.x * 256 + tid;
    int o = g_offs[i] + g_bbase[blockIdx.x];
    g_offs[i] = o;
    g_cursor[i] = o;
    g_dis[i] = rsqrtf((float)(g_cnt[i] + 1));
    if (i == 0) g_offs[Nn] = Ee;
}

__global__ void scan_batch_kernel() {
    __shared__ int sbuf[Bb];
    int tid = threadIdx.x;
    int c = g_bcnt[tid];
    sbuf[tid] = c;
    __syncthreads();
    for (int off = 1; off < Bb; off <<= 1) {
        int v = (tid >= off) ? sbuf[tid - off] : 0;
        __syncthreads();
        sbuf[tid] += v;
        __syncthreads();
    }
    g_starts[tid] = sbuf[tid] - c;
}

__global__ void fill_kernel(const int* __restrict__ row, const int* __restrict__ col) {
    int e = blockIdx.x * blockDim.x + threadIdx.x;
    if (e >= Ee) return;
    int p = atomicAdd(&g_cursor[col[e]], 1);
    g_csr[p] = row[e];
}

// ---------------- synthetic gather PROBE (profiling only) -------------------
// Same memory pattern as gather_kernel (warp/node, 8 hash-random 128B rows);
// deterministic; writes Agg rows that agg0 fully overwrites afterwards.
__global__ void __launch_bounds__(256) gather_probe_kernel() {
    int gt = blockIdx.x * blockDim.x + threadIdx.x;
    int n = gt >> 5, lane = gt & 31;
    const float4* Y4 = (const float4*)g_Y;
    float4 acc = make_float4(0.f, 0.f, 0.f, 0.f);
    unsigned int h = (unsigned int)n * 2654435761u;
    #pragma unroll
    for (int j = 0; j < 8; ++j) {
        int r = (h >> 8) & (Nn - 1);
        h = h * 1664525u + 1013904223u;
        float4 v = Y4[(size_t)r * 32 + lane];
        acc.x += v.x; acc.y += v.y; acc.z += v.z; acc.w += v.w;
    }
    ((float4*)g_Agg)[(size_t)n * 32 + lane] = acc;
}

// ---------------- layer-0 aggregation ---------------------------------------
__global__ void __launch_bounds__(256) agg0_kernel(const int* __restrict__ z) {
    __shared__ float bins[8][128];
    int w = threadIdx.x >> 5, lane = threadIdx.x & 31;
    int n = blockIdx.x * 8 + w;
    ((float4*)bins[w])[lane] = make_float4(0.f, 0.f, 0.f, 0.f);
    __syncwarp();
    int s = g_offs[n], e = g_offs[n + 1];
    for (int j = s + lane; j < e; j += 32) {
        int r = g_csr[j];
        atomicAdd(&bins[w][z[r]], g_dis[r]);
    }
    __syncwarp();
    if (lane == 0) bins[w][z[n]] += g_dis[n];
    __syncwarp();
    float dc = g_dis[n];
    float4 b = ((float4*)bins[w])[lane];
    b.x *= dc; b.y *= dc; b.z *= dc; b.w *= dc;
    ((float4*)(g_Agg + (size_t)n * HID))[lane] = b;
}

// ---------------- layers 1/2: CSR gather ------------------------------------
__global__ void __launch_bounds__(256) gather_kernel() {
    int gt = blockIdx.x * blockDim.x + threadIdx.x;
    int n = gt >> 5, lane = gt & 31;
    const float4* Y4 = (const float4*)g_Y;
    float4 acc = Y4[(size_t)n * 32 + lane];
    float4 acc2 = make_float4(0.f, 0.f, 0.f, 0.f);
    int s = g_offs[n], e = g_offs[n + 1];
    int j = s;
    for (; j + 2 <= e; j += 2) {
        int r0 = g_csr[j], r1 = g_csr[j + 1];
        float4 v0 = Y4[(size_t)r0 * 32 + lane];
        float4 v1 = Y4[(size_t)r1 * 32 + lane];
        acc.x += v0.x; acc.y += v0.y; acc.z += v0.z; acc.w += v0.w;
        acc2.x += v1.x; acc2.y += v1.y; acc2.z += v1.z; acc2.w += v1.w;
    }
    if (j < e) {
        int r = g_csr[j];
        float4 v = Y4[(size_t)r * 32 + lane];
        acc.x += v.x; acc.y += v.y; acc.z += v.z; acc.w += v.w;
    }
    acc.x += acc2.x; acc.y += acc2.y; acc.z += acc2.z; acc.w += acc2.w;
    float dc = g_dis[n];
    acc.x *= dc; acc.y *= dc; acc.z *= dc; acc.w *= dc;
    ((float4*)(g_Agg))[(size_t)n * 32 + lane] = acc;
}

// ---------------- GEMM v3: 64x128 tile, 256 thr, packed-row f32x2 -----------
// As stored transposed (stride 66) so LDS.64 yields a row-pair; Ws staged
// duplicated (w,w) so FFMA2 consumes it directly. 4 rows x 8 cols per thread.
#define AST 66
__global__ void __launch_bounds__(256) gemm_tanh_kernel(const float* __restrict__ W,
                                                        const float* __restrict__ bias,
                                                        int out_off, int writeY) {
    __shared__ float AsT[128 * AST];        // [k][r], r stride-1
    __shared__ float Wd[16 * 256];          // [kk][2c] duplicated pairs
    int t = threadIdx.x;
    int rbase = blockIdx.x * 64;
    int tx = t & 15, ty = t >> 4;           // tx: col group (8 cols), ty: row group (4 rows)
    int col0 = tx * 8, row0 = ty * 4;

    // stage A transposed
    {
        const float4* A4 = (const float4*)(g_Agg + (size_t)rbase * HID);
        #pragma unroll
        for (int i = 0; i < 8; ++i) {
            int idx = t + i * 256;
            int r = idx >> 5, c4 = idx & 31;
            float4 v = A4[idx];
            AsT[(4 * c4 + 0) * AST + r] = v.x;
            AsT[(4 * c4 + 1) * AST + r] = v.y;
            AsT[(4 * c4 + 2) * AST + r] = v.z;
            AsT[(4 * c4 + 3) * AST + r] = v.w;
        }
    }

    unsigned long long acc[2][8];
    #pragma unroll
    for (int p = 0; p < 2; ++p)
        #pragma unroll
        for (int c = 0; c < 8; ++c) acc[p][c] = 0ull;

    for (int kc = 0; kc < 8; ++kc) {
        __syncthreads();
        // stage 16 k-rows of W duplicated: Wd[kk*256 + 2c{+1}] = W[(kc*16+kk)*128 + c]
        {
            const float4* W4 = (const float4*)(W + kc * 16 * 128);
            #pragma unroll
            for (int i = 0; i < 2; ++i) {
                int idx = t + i * 256;                // 0..511
                int kk = idx >> 5, c0 = (idx & 31) * 4;
                float4 v = W4[idx];
                float* d = Wd + kk * 256 + 2 * c0;
                *(float4*)(d)     = make_float4(v.x, v.x, v.y, v.y);
                *(float4*)(d + 4) = make_float4(v.z, v.z, v.w, v.w);
            }
        }
        __syncthreads();
        #pragma unroll
        for (int kk = 0; kk < 16; ++kk) {
            int k = kc * 16 + kk;
            unsigned long long a0 = *(const unsigned long long*)(AsT + k * AST + row0);
            unsigned long long a1 = *(const unsigned long long*)(AsT + k * AST + row0 + 2);
            const unsigned long long* wr = (const unsigned long long*)(Wd + kk * 256 + 2 * col0);
            unsigned long long w0 = wr[0], w1 = wr[1], w2 = wr[2], w3 = wr[3],
                               w4 = wr[4], w5 = wr[5], w6 = wr[6], w7 = wr[7];
            FMAF2(acc[0][0], a0, w0); FMAF2(acc[0][1], a0, w1);
            FMAF2(acc[0][2], a0, w2); FMAF2(acc[0][3], a0, w3);
            FMAF2(acc[0][4], a0, w4); FMAF2(acc[0][5], a0, w5);
            FMAF2(acc[0][6], a0, w6); FMAF2(acc[0][7], a0, w7);
            FMAF2(acc[1][0], a1, w0); FMAF2(acc[1][1], a1, w1);
            FMAF2(acc[1][2], a1, w2); FMAF2(acc[1][3], a1, w3);
            FMAF2(acc[1][4], a1, w4); FMAF2(acc[1][5], a1, w5);
            FMAF2(acc[1][6], a1, w6); FMAF2(acc[1][7], a1, w7);
        }
    }

    float bv[8];
    #pragma unroll
    for (int c = 0; c < 8; ++c) bv[c] = __ldg(&bias[col0 + c]);

    #pragma unroll
    for (int r = 0; r < 4; ++r) {
        int p = r >> 1, hi = r & 1;
        int rown = rbase + row0 + r;
        float dr = g_dis[rown];
        float v[8];
        #pragma unroll
        for (int c = 0; c < 8; ++c) {
            float lo, hf;
            UNPACKF2(lo, hf, acc[p][c]);
            v[c] = hi ? hf : lo;
        }
        #pragma unroll
        for (int c = 0; c < 8; ++c) v[c] = tanhf(v[c] + bv[c]);
        float* o = g_X + (size_t)rown * DD + out_off + col0;
        *(float4*)(o)     = make_float4(v[0], v[1], v[2], v[3]);
        *(float4*)(o + 4) = make_float4(v[4], v[5], v[6], v[7]);
        if (writeY) {
            float* y = g_Y + (size_t)rown * HID + col0;
            *(float4*)(y)     = make_float4(v[0]*dr, v[1]*dr, v[2]*dr, v[3]*dr);
            *(float4*)(y + 4) = make_float4(v[4]*dr, v[5]*dr, v[6]*dr, v[7]*dr);
        }
    }
}

// ---------------- per-graph head --------------------------------------------
__global__ void __launch_bounds__(256) head_kernel(
        const float* __restrict__ Wc1, const float* __restrict__ bc1,
        const float* __restrict__ Wc2, const float* __restrict__ bc2,
        const float* __restrict__ g1,  const float* __restrict__ be1,
        const float* __restrict__ g2,  const float* __restrict__ be2,
        const float* __restrict__ Wl1, const float* __restrict__ bl1,
        const float* __restrict__ Wl2, const float* __restrict__ bl2,
        const float* __restrict__ rm1, const float* __restrict__ rv1,
        const float* __restrict__ rm2, const float* __restrict__ rv2,
        float* __restrict__ out) {
    __shared__ float keys[SMAX];
    __shared__ int   topk[KK];
    __shared__ float Wc1s[C1n * DD];
    __shared__ float c1s[C1n * KK];
    __shared__ float h2s[C2n * L2n];
    __shared__ float ps[FLAT];
    __shared__ float f1[128];
    __shared__ float red[256];

    int b = blockIdx.x, tid = threadIdx.x, bd = blockDim.x;
    int M = g_bcnt[b];
    if (M > SMAX) M = SMAX;
    int s = g_starts[b];

    for (int i = tid; i < C1n * DD; i += bd) Wc1s[i] = Wc1[i];
    for (int i = tid; i < M; i += bd) keys[i] = g_X[(size_t)(s + i) * DD + (DD - 1)];
    for (int i = tid; i < KK; i += bd) topk[i] = -1;
    __syncthreads();

    for (int i = tid; i < M; i += bd) {
        float ki = keys[i];
        int r = 0;
        for (int j = 0; j < M; ++j) {
            float kj = keys[j];
            r += (kj > ki) || (kj == ki && j < i);
        }
        if (r < KK) topk[r] = s + i;
    }
    __syncthreads();

    for (int o = tid; o < C1n * KK; o += bd) {
        int c = o & 15, k = o >> 4;
        int node = topk[k];
        float acc = __ldg(&bc1[c]);
        if (node >= 0) {
            const float* xr = g_X + (size_t)node * DD;
            const float* w = Wc1s + c * DD;
            #pragma unroll 4
            for (int d = 0; d < DD; ++d) acc += xr[d] * w[d];
        }
        float v = fmaxf(acc, 0.f);
        v = (v - __ldg(&rm1[c])) * (__ldg(&g1[c]) * rsqrtf(__ldg(&rv1[c]) + EPSc)) + __ldg(&be1[c]);
        c1s[c * KK + k] = v;
    }
    __syncthreads();

    for (int o = tid; o < C2n * L2n; o += bd) {
        int oc = o / L2n, tt = o % L2n;
        float acc = __ldg(&bc2[oc]);
        const float* w = Wc2 + oc * (C1n * KERNL);
        for (int ic = 0; ic < C1n; ++ic) {
            #pragma unroll
            for (int kk = 0; kk < KERNL; ++kk)
                acc += c1s[ic * KK + tt + kk] * __ldg(&w[ic * KERNL + kk]);
        }
        float v = fmaxf(acc, 0.f);
        v = (v - __ldg(&rm2[oc])) * (__ldg(&g2[oc]) * rsqrtf(__ldg(&rv2[oc]) + EPSc)) + __ldg(&be2[oc]);
        h2s[oc * L2n + tt] = v;
    }
    __syncthreads();

    for (int o = tid; o < FLAT; o += bd) {
        int oc = o / PL, l = o % PL;
        ps[o] = fmaxf(h2s[oc * L2n + 2 * l], h2s[oc * L2n + 2 * l + 1]);
    }
    __syncthreads();

    for (int j = tid; j < 128; j += bd) {
        float acc = __ldg(&bl1[j]);
        const float* w = Wl1 + j * FLAT;
        #pragma unroll 4
        for (int i = 0; i < FLAT; ++i) acc += ps[i] * __ldg(&w[i]);
        f1[j] = fmaxf(acc, 0.f);
    }
    __syncthreads();

    float p = 0.f;
    if (tid < 128) p = f1[tid] * __ldg(&Wl2[tid]);
    red[tid] = p;
    __syncthreads();
    for (int off = 128; off > 0; off >>= 1) {
        if (tid < off && tid + off < bd) red[tid] += red[tid + off];
        __syncthreads();
    }
    if (tid == 0) out[b] = red[0] + __ldg(&bl2[0]);
}

// ---------------- host orchestration ----------------------------------------
extern "C" void kernel_launch(void* const* d_in, const int* in_sizes, int n_in,
                              void* d_out, int out_size) {
    const int*   z     = (const int*)d_in[0];
    const int*   ei    = (const int*)d_in[1];
    const int*   batch = (const int*)d_in[2];
    const float* W0    = (const float*)d_in[3];
    const float* b0    = (const float*)d_in[4];
    const float* W1    = (const float*)d_in[5];
    const float* b1    = (const float*)d_in[6];
    const float* W2    = (const float*)d_in[7];
    const float* b2    = (const float*)d_in[8];
    const float* Wc1   = (const float*)d_in[9];
    const float* bc1   = (const float*)d_in[10];
    const float* Wc2   = (const float*)d_in[11];
    const float* bc2   = (const float*)d_in[12];
    const float* g1    = (const float*)d_in[13];
    const float* be1   = (const float*)d_in[14];
    const float* g2    = (const float*)d_in[15];
    const float* be2   = (const float*)d_in[16];
    const float* Wl1   = (const float*)d_in[17];
    const float* bl1   = (const float*)d_in[18];
    const float* Wl2   = (const float*)d_in[19];
    const float* bl2   = (const float*)d_in[20];
    const float* rm1   = (const float*)d_in[21];
    const float* rv1   = (const float*)d_in[22];
    const float* rm2   = (const float*)d_in[23];
    const float* rv2   = (const float*)d_in[24];
    float* out = (float*)d_out;

    const int* row = ei;
    const int* col = ei + Ee;

    init_kernel<<<(Nn + 255) / 256, 256>>>();                 // 0
    count_kernel<<<(Ee + 255) / 256, 256>>>(col, batch);      // 1
    scanA_kernel<<<SCANB, 256>>>();                           // 2
    gather_probe_kernel<<<4096, 256>>>();                     // 3  <-- profiled
    scanB_kernel<<<1, SCANB>>>();                             // 4
    scanC_kernel<<<SCANB, 256>>>();                           // 5
    scan_batch_kernel<<<1, Bb>>>();                           // 6
    fill_kernel<<<(Ee + 255) / 256, 256>>>(row, col);         // 7

    agg0_kernel<<<Nn / 8, 256>>>(z);                          // 8
    gemm_tanh_kernel<<<Nn / 64, 256>>>(W0, b0, 0, 1);         // 9

    gather_kernel<<<Nn * 32 / 256, 256>>>();                  // 10
    gemm_tanh_kernel<<<Nn / 64, 256>>>(W1, b1, HID, 1);       // 11

    gather_kernel<<<Nn * 32 / 256, 256>>>();                  // 12
    gemm_tanh_kernel<<<Nn / 64, 256>>>(W2, b2, 2 * HID, 0);   // 13

    head_kernel<<<Bb, 256>>>(Wc1, bc1, Wc2, bc2, g1, be1, g2, be2,
                             Wl1, bl1, Wl2, bl2, rm1, rv1, rm2, rv2, out);  // 14
}

// round 6
// speedup vs baseline: 1.7413x; 1.7413x over previous
#include <cuda_runtime.h>
#include <math.h>

// Problem constants
#define Nn   131072
#define Ee   1048576
#define Bb   1024
#define FIN  128
#define HID  128
#define DD   384
#define KK   30
#define C1n  16
#define C2n  32
#define KERNL 5
#define L2n  26
#define PL   13
#define FLAT 416
#define EPSc 1e-5f
#define SMAX 2048
#define SCANB 512

// packed fp32x2 helpers
#define PACKF2(out, lo, hi) \
    asm("mov.b64 %0, {%1, %2};" : "=l"(out) : "r"(__float_as_uint(lo)), "r"(__float_as_uint(hi)))
#define UNPACKF2(lo, hi, in) \
    { unsigned int _a, _b; asm("mov.b64 {%0, %1}, %2;" : "=r"(_a), "=r"(_b) : "l"(in)); \
      lo = __uint_as_float(_a); hi = __uint_as_float(_b); }
#define FMAF2(acc, a, b) \
    asm("fma.rn.f32x2 %0, %1, %2, %0;" : "+l"(acc) : "l"(a), "l"(b))

// ---------------- scratch ----------------------------------------------------
__device__ float g_dis[Nn];
__device__ int   g_cnt[Nn];
__device__ int   g_offs[Nn + 1];
__device__ int   g_cursor[Nn];
__device__ int   g_csr[Ee];
__device__ float g_Agg[(size_t)Nn * HID];
__device__ float g_Y[(size_t)Nn * HID];
__device__ float g_X[(size_t)Nn * DD];
__device__ int   g_bcnt[Bb];
__device__ int   g_starts[Bb];
__device__ int   g_bsum[SCANB];
__device__ int   g_bbase[SCANB];

// ---------------- init -------------------------------------------------------
__global__ void init_kernel() {
    int i = blockIdx.x * blockDim.x + threadIdx.x;
    if (i < Nn) g_cnt[i] = 0;
    if (i < Bb) g_bcnt[i] = 0;
}

__global__ void count_kernel(const int* __restrict__ col, const int* __restrict__ batch) {
    int e = blockIdx.x * blockDim.x + threadIdx.x;
    if (e < Ee) atomicAdd(&g_cnt[col[e]], 1);
    if (e < Nn) atomicAdd(&g_bcnt[batch[e]], 1);
}

// ---------------- hierarchical scan over node counts ------------------------
__global__ void scanA_kernel() {
    __shared__ int s[256];
    int tid = threadIdx.x;
    int i = blockIdx.x * 256 + tid;
    int c = g_cnt[i];
    s[tid] = c;
    __syncthreads();
    #pragma unroll
    for (int off = 1; off < 256; off <<= 1) {
        int v = (tid >= off) ? s[tid - off] : 0;
        __syncthreads();
        s[tid] += v;
        __syncthreads();
    }
    g_offs[i] = s[tid] - c;
    if (tid == 255) g_bsum[blockIdx.x] = s[255];
}

__global__ void scanB_kernel() {
    __shared__ int s[SCANB];
    int tid = threadIdx.x;
    int c = g_bsum[tid];
    s[tid] = c;
    __syncthreads();
    for (int off = 1; off < SCANB; off <<= 1) {
        int v = (tid >= off) ? s[tid - off] : 0;
        __syncthreads();
        s[tid] += v;
        __syncthreads();
    }
    g_bbase[tid] = s[tid] - c;
}

__global__ void scanC_kernel() {
    int tid = threadIdx.x;
    int i = blockIdx.x * 256 + tid;
    int o = g_offs[i] + g_bbase[blockIdx.x];
    g_offs[i] = o;
    g_cursor[i] = o;
    g_dis[i] = rsqrtf((float)(g_cnt[i] + 1));
    if (i == 0) g_offs[Nn] = Ee;
}

__global__ void scan_batch_kernel() {
    __shared__ int sbuf[Bb];
    int tid = threadIdx.x;
    int c = g_bcnt[tid];
    sbuf[tid] = c;
    __syncthreads();
    for (int off = 1; off < Bb; off <<= 1) {
        int v = (tid >= off) ? sbuf[tid - off] : 0;
        __syncthreads();
        sbuf[tid] += v;
        __syncthreads();
    }
    g_starts[tid] = sbuf[tid] - c;
}

__global__ void fill_kernel(const int* __restrict__ row, const int* __restrict__ col) {
    int e = blockIdx.x * blockDim.x + threadIdx.x;
    if (e >= Ee) return;
    int p = atomicAdd(&g_cursor[col[e]], 1);
    g_csr[p] = row[e];
}

// ---------------- layer-0 aggregation ---------------------------------------
__global__ void __launch_bounds__(256) agg0_kernel(const int* __restrict__ z) {
    __shared__ float bins[8][128];
    int w = threadIdx.x >> 5, lane = threadIdx.x & 31;
    int n = blockIdx.x * 8 + w;
    ((float4*)bins[w])[lane] = make_float4(0.f, 0.f, 0.f, 0.f);
    __syncwarp();
    int s = g_offs[n], e = g_offs[n + 1];
    for (int j = s + lane; j < e; j += 32) {
        int r = g_csr[j];
        atomicAdd(&bins[w][z[r]], g_dis[r]);
    }
    __syncwarp();
    if (lane == 0) bins[w][z[n]] += g_dis[n];
    __syncwarp();
    float dc = g_dis[n];
    float4 b = ((float4*)bins[w])[lane];
    b.x *= dc; b.y *= dc; b.z *= dc; b.w *= dc;
    ((float4*)(g_Agg + (size_t)n * HID))[lane] = b;
}

// ---------------- layers 1/2: CSR gather ------------------------------------
__global__ void __launch_bounds__(256) gather_kernel() {
    int gt = blockIdx.x * blockDim.x + threadIdx.x;
    int n = gt >> 5, lane = gt & 31;
    const float4* Y4 = (const float4*)g_Y;
    float4 acc = Y4[(size_t)n * 32 + lane];
    float4 acc2 = make_float4(0.f, 0.f, 0.f, 0.f);
    int s = g_offs[n], e = g_offs[n + 1];
    int j = s;
    for (; j + 2 <= e; j += 2) {
        int r0 = g_csr[j], r1 = g_csr[j + 1];
        float4 v0 = Y4[(size_t)r0 * 32 + lane];
        float4 v1 = Y4[(size_t)r1 * 32 + lane];
        acc.x += v0.x; acc.y += v0.y; acc.z += v0.z; acc.w += v0.w;
        acc2.x += v1.x; acc2.y += v1.y; acc2.z += v1.z; acc2.w += v1.w;
    }
    if (j < e) {
        int r = g_csr[j];
        float4 v = Y4[(size_t)r * 32 + lane];
        acc.x += v.x; acc.y += v.y; acc.z += v.z; acc.w += v.w;
    }
    acc.x += acc2.x; acc.y += acc2.y; acc.z += acc2.z; acc.w += acc2.w;
    float dc = g_dis[n];
    acc.x *= dc; acc.y *= dc; acc.z *= dc; acc.w *= dc;
    ((float4*)(g_Agg))[(size_t)n * 32 + lane] = acc;
}

// ---------------- GEMM v4: 64x128 tile, 256 thr, row-pair f32x2 -------------
// A row-major in smem (stride 132). W staged as duplicated (w,w) pairs with
// interleaved column ownership: thread tx owns cols {tx, tx+16, ..., tx+112},
// so the 8 W-pair LDS.64 per k sit at 8B lane stride (conflict-free).
#define AROWS 132
__global__ void __launch_bounds__(256) gemm_tanh_kernel(const float* __restrict__ W,
                                                        const float* __restrict__ bias,
                                                        int out_off, int writeY) {
    __shared__ float As[64 * AROWS];
    __shared__ float Wd[16 * 256];          // [kk][2c] duplicated pairs
    int t = threadIdx.x;
    int rbase = blockIdx.x * 64;
    int tx = t & 15, ty = t >> 4;           // ty: 16 row groups of 4 rows
    int row0 = ty * 4;

    // stage A row-major (coalesced, padded stride)
    {
        const float4* A4 = (const float4*)(g_Agg + (size_t)rbase * HID);
        #pragma unroll
        for (int i = 0; i < 8; ++i) {
            int idx = t + i * 256;
            int r = idx >> 5, c4 = idx & 31;
            *(float4*)(As + r * AROWS + c4 * 4) = A4[idx];
        }
    }

    unsigned long long acc[2][8];           // [row-pair][col j]
    #pragma unroll
    for (int p = 0; p < 2; ++p)
        #pragma unroll
        for (int j = 0; j < 8; ++j) acc[p][j] = 0ull;

    for (int kc = 0; kc < 8; ++kc) {
        __syncthreads();
        // stage 16 k-rows of W duplicated: Wd[kk*256 + 2c{,+1}] = W[(kc*16+kk)*128 + c]
        {
            const float4* W4 = (const float4*)(W + kc * 16 * 128);
            #pragma unroll
            for (int i = 0; i < 2; ++i) {
                int idx = t + i * 256;
                int kk = idx >> 5, c0 = (idx & 31) * 4;
                float4 v = W4[idx];
                float* d = Wd + kk * 256 + 2 * c0;
                *(float4*)(d)     = make_float4(v.x, v.x, v.y, v.y);
                *(float4*)(d + 4) = make_float4(v.z, v.z, v.w, v.w);
            }
        }
        __syncthreads();
        #pragma unroll
        for (int kk = 0; kk < 16; ++kk) {
            int k = kc * 16 + kk;
            float a00 = As[(row0 + 0) * AROWS + k];
            float a01 = As[(row0 + 1) * AROWS + k];
            float a10 = As[(row0 + 2) * AROWS + k];
            float a11 = As[(row0 + 3) * AROWS + k];
            unsigned long long a0, a1;
            PACKF2(a0, a00, a01);
            PACKF2(a1, a10, a11);
            const float* wbase = Wd + kk * 256 + 2 * tx;   // 8B lane stride
            #pragma unroll
            for (int j = 0; j < 8; ++j) {
                unsigned long long w = *(const unsigned long long*)(wbase + 32 * j);
                FMAF2(acc[0][j], a0, w);
                FMAF2(acc[1][j], a1, w);
            }
        }
    }

    float bv[8];
    #pragma unroll
    for (int j = 0; j < 8; ++j) bv[j] = __ldg(&bias[tx + 16 * j]);

    #pragma unroll
    for (int r = 0; r < 4; ++r) {
        int p = r >> 1, hi = r & 1;
        int rown = rbase + row0 + r;
        float dr = g_dis[rown];
        float* o = g_X + (size_t)rown * DD + out_off;
        float* y = g_Y + (size_t)rown * HID;
        #pragma unroll
        for (int j = 0; j < 8; ++j) {
            float lo, hf;
            UNPACKF2(lo, hf, acc[p][j]);
            float v = tanhf((hi ? hf : lo) + bv[j]);
            o[tx + 16 * j] = v;
            if (writeY) y[tx + 16 * j] = v * dr;
        }
    }
}

// ---------------- per-graph head --------------------------------------------
__global__ void __launch_bounds__(256) head_kernel(
        const float* __restrict__ Wc1, const float* __restrict__ bc1,
        const float* __restrict__ Wc2, const float* __restrict__ bc2,
        const float* __restrict__ g1,  const float* __restrict__ be1,
        const float* __restrict__ g2,  const float* __restrict__ be2,
        const float* __restrict__ Wl1, const float* __restrict__ bl1,
        const float* __restrict__ Wl2, const float* __restrict__ bl2,
        const float* __restrict__ rm1, const float* __restrict__ rv1,
        const float* __restrict__ rm2, const float* __restrict__ rv2,
        float* __restrict__ out) {
    __shared__ float keys[SMAX];
    __shared__ int   topk[KK];
    __shared__ float Wc1s[C1n * DD];
    __shared__ float c1s[C1n * KK];
    __shared__ float h2s[C2n * L2n];
    __shared__ float ps[FLAT];
    __shared__ float f1[128];
    __shared__ float red[256];

    int b = blockIdx.x, tid = threadIdx.x, bd = blockDim.x;
    int M = g_bcnt[b];
    if (M > SMAX) M = SMAX;
    int s = g_starts[b];

    for (int i = tid; i < C1n * DD; i += bd) Wc1s[i] = Wc1[i];
    for (int i = tid; i < M; i += bd) keys[i] = g_X[(size_t)(s + i) * DD + (DD - 1)];
    for (int i = tid; i < KK; i += bd) topk[i] = -1;
    __syncthreads();

    for (int i = tid; i < M; i += bd) {
        float ki = keys[i];
        int r = 0;
        for (int j = 0; j < M; ++j) {
            float kj = keys[j];
            r += (kj > ki) || (kj == ki && j < i);
        }
        if (r < KK) topk[r] = s + i;
    }
    __syncthreads();

    for (int o = tid; o < C1n * KK; o += bd) {
        int c = o & 15, k = o >> 4;
        int node = topk[k];
        float acc = __ldg(&bc1[c]);
        if (node >= 0) {
            const float* xr = g_X + (size_t)node * DD;
            const float* w = Wc1s + c * DD;
            #pragma unroll 4
            for (int d = 0; d < DD; ++d) acc += xr[d] * w[d];
        }
        float v = fmaxf(acc, 0.f);
        v = (v - __ldg(&rm1[c])) * (__ldg(&g1[c]) * rsqrtf(__ldg(&rv1[c]) + EPSc)) + __ldg(&be1[c]);
        c1s[c * KK + k] = v;
    }
    __syncthreads();

    for (int o = tid; o < C2n * L2n; o += bd) {
        int oc = o / L2n, tt = o % L2n;
        float acc = __ldg(&bc2[oc]);
        const float* w = Wc2 + oc * (C1n * KERNL);
        for (int ic = 0; ic < C1n; ++ic) {
            #pragma unroll
            for (int kk = 0; kk < KERNL; ++kk)
                acc += c1s[ic * KK + tt + kk] * __ldg(&w[ic * KERNL + kk]);
        }
        float v = fmaxf(acc, 0.f);
        v = (v - __ldg(&rm2[oc])) * (__ldg(&g2[oc]) * rsqrtf(__ldg(&rv2[oc]) + EPSc)) + __ldg(&be2[oc]);
        h2s[oc * L2n + tt] = v;
    }
    __syncthreads();

    for (int o = tid; o < FLAT; o += bd) {
        int oc = o / PL, l = o % PL;
        ps[o] = fmaxf(h2s[oc * L2n + 2 * l], h2s[oc * L2n + 2 * l + 1]);
    }
    __syncthreads();

    for (int j = tid; j < 128; j += bd) {
        float acc = __ldg(&bl1[j]);
        const float* w = Wl1 + j * FLAT;
        #pragma unroll 4
        for (int i = 0; i < FLAT; ++i) acc += ps[i] * __ldg(&w[i]);
        f1[j] = fmaxf(acc, 0.f);
    }
    __syncthreads();

    float p = 0.f;
    if (tid < 128) p = f1[tid] * __ldg(&Wl2[tid]);
    red[tid] = p;
    __syncthreads();
    for (int off = 128; off > 0; off >>= 1) {
        if (tid < off && tid + off < bd) red[tid] += red[tid + off];
        __syncthreads();
    }
    if (tid == 0) out[b] = red[0] + __ldg(&bl2[0]);
}

// ---------------- host orchestration ----------------------------------------
extern "C" void kernel_launch(void* const* d_in, const int* in_sizes, int n_in,
                              void* d_out, int out_size) {
    const int*   z     = (const int*)d_in[0];
    const int*   ei    = (const int*)d_in[1];
    const int*   batch = (const int*)d_in[2];
    const float* W0    = (const float*)d_in[3];
    const float* b0    = (const float*)d_in[4];
    const float* W1    = (const float*)d_in[5];
    const float* b1    = (const float*)d_in[6];
    const float* W2    = (const float*)d_in[7];
    const float* b2    = (const float*)d_in[8];
    const float* Wc1   = (const float*)d_in[9];
    const float* bc1   = (const float*)d_in[10];
    const float* Wc2   = (const float*)d_in[11];
    const float* bc2   = (const float*)d_in[12];
    const float* g1    = (const float*)d_in[13];
    const float* be1   = (const float*)d_in[14];
    const float* g2    = (const float*)d_in[15];
    const float* be2   = (const float*)d_in[16];
    const float* Wl1   = (const float*)d_in[17];
    const float* bl1   = (const float*)d_in[18];
    const float* Wl2   = (const float*)d_in[19];
    const float* bl2   = (const float*)d_in[20];
    const float* rm1   = (const float*)d_in[21];
    const float* rv1   = (const float*)d_in[22];
    const float* rm2   = (const float*)d_in[23];
    const float* rv2   = (const float*)d_in[24];
    float* out = (float*)d_out;

    const int* row = ei;
    const int* col = ei + Ee;

    init_kernel<<<(Nn + 255) / 256, 256>>>();                 // 0
    count_kernel<<<(Ee + 255) / 256, 256>>>(col, batch);      // 1
    scanA_kernel<<<SCANB, 256>>>();                           // 2
    // PROBE (profiled slot): quarter-size GEMM v4 on scratch; outputs fully
    // overwritten by the real pipeline below.
    gemm_tanh_kernel<<<512, 256>>>(W0, b0, 0, 1);             // 3  <-- profiled
    scanB_kernel<<<1, SCANB>>>();                             // 4
    scanC_kernel<<<SCANB, 256>>>();                           // 5
    scan_batch_kernel<<<1, Bb>>>();                           // 6
    fill_kernel<<<(Ee + 255) / 256, 256>>>(row, col);         // 7

    agg0_kernel<<<Nn / 8, 256>>>(z);                          // 8
    gemm_tanh_kernel<<<Nn / 64, 256>>>(W0, b0, 0, 1);         // 9

    gather_kernel<<<Nn * 32 / 256, 256>>>();                  // 10
    gemm_tanh_kernel<<<Nn / 64, 256>>>(W1, b1, HID, 1);       // 11

    gather_kernel<<<Nn * 32 / 256, 256>>>();                  // 12
    gemm_tanh_kernel<<<Nn / 64, 256>>>(W2, b2, 2 * HID, 0);   // 13

    head_kernel<<<Bb, 256>>>(Wc1, bc1, Wc2, bc2, g1, be1, g2, be2,
                             Wl1, bl1, Wl2, bl2, rm1, rv1, rm2, rv2, out);  // 14
}

// round 9
// speedup vs baseline: 2.1147x; 1.2144x over previous
#include <cuda_runtime.h>
#include <math.h>

// Problem constants
#define Nn   131072
#define Ee   1048576
#define Bb   1024
#define FIN  128
#define HID  128
#define DD   384
#define KK   30
#define C1n  16
#define C2n  32
#define KERNL 5
#define L2n  26
#define PL   13
#define FLAT 416
#define EPSc 1e-5f
#define SMAX 2048
#define SCANB 512

// packed fp32x2 helpers
#define PACKF2(out, lo, hi) \
    asm("mov.b64 %0, {%1, %2};" : "=l"(out) : "r"(__float_as_uint(lo)), "r"(__float_as_uint(hi)))
#define UNPACKF2(lo, hi, in) \
    { unsigned int _a, _b; asm("mov.b64 {%0, %1}, %2;" : "=r"(_a), "=r"(_b) : "l"(in)); \
      lo = __uint_as_float(_a); hi = __uint_as_float(_b); }
#define FMAF2(acc, a, b) \
    asm("fma.rn.f32x2 %0, %1, %2, %0;" : "+l"(acc) : "l"(a), "l"(b))

// ---------------- scratch ----------------------------------------------------
__device__ float g_dis[Nn];
__device__ int   g_cnt[Nn];
__device__ int   g_offs[Nn + 1];
__device__ int   g_cursor[Nn];
__device__ int   g_csr[Ee];
__device__ float g_Agg[(size_t)Nn * HID];
__device__ float g_Y[(size_t)Nn * HID];
__device__ float g_X[(size_t)Nn * DD];
__device__ int   g_bcnt[Bb];
__device__ int   g_starts[Bb];
__device__ int   g_bsum[SCANB];
__device__ int   g_bbase[SCANB];

// ---------------- init -------------------------------------------------------
__global__ void init_kernel() {
    int i = blockIdx.x * blockDim.x + threadIdx.x;
    if (i < Nn) g_cnt[i] = 0;
    if (i < Bb) g_bcnt[i] = 0;
}

__global__ void count_kernel(const int* __restrict__ col, const int* __restrict__ batch) {
    int e = blockIdx.x * blockDim.x + threadIdx.x;
    if (e < Ee) atomicAdd(&g_cnt[col[e]], 1);
    if (e < Nn) atomicAdd(&g_bcnt[batch[e]], 1);
}

// ---------------- hierarchical scan over node counts ------------------------
__global__ void scanA_kernel() {
    __shared__ int s[256];
    int tid = threadIdx.x;
    int i = blockIdx.x * 256 + tid;
    int c = g_cnt[i];
    s[tid] = c;
    __syncthreads();
    #pragma unroll
    for (int off = 1; off < 256; off <<= 1) {
        int v = (tid >= off) ? s[tid - off] : 0;
        __syncthreads();
        s[tid] += v;
        __syncthreads();
    }
    g_offs[i] = s[tid] - c;
    if (tid == 255) g_bsum[blockIdx.x] = s[255];
}

__global__ void scanB_kernel() {
    __shared__ int s[SCANB];
    int tid = threadIdx.x;
    int c = g_bsum[tid];
    s[tid] = c;
    __syncthreads();
    for (int off = 1; off < SCANB; off <<= 1) {
        int v = (tid >= off) ? s[tid - off] : 0;
        __syncthreads();
        s[tid] += v;
        __syncthreads();
    }
    g_bbase[tid] = s[tid] - c;
}

__global__ void scanC_kernel() {
    int tid = threadIdx.x;
    int i = blockIdx.x * 256 + tid;
    int o = g_offs[i] + g_bbase[blockIdx.x];
    g_offs[i] = o;
    g_cursor[i] = o;
    g_dis[i] = rsqrtf((float)(g_cnt[i] + 1));
    if (i == 0) g_offs[Nn] = Ee;
}

__global__ void scan_batch_kernel() {
    __shared__ int sbuf[Bb];
    int tid = threadIdx.x;
    int c = g_bcnt[tid];
    sbuf[tid] = c;
    __syncthreads();
    for (int off = 1; off < Bb; off <<= 1) {
        int v = (tid >= off) ? sbuf[tid - off] : 0;
        __syncthreads();
        sbuf[tid] += v;
        __syncthreads();
    }
    g_starts[tid] = sbuf[tid] - c;
}

__global__ void fill_kernel(const int* __restrict__ row, const int* __restrict__ col) {
    int e = blockIdx.x * blockDim.x + threadIdx.x;
    if (e >= Ee) return;
    int p = atomicAdd(&g_cursor[col[e]], 1);
    g_csr[p] = row[e];
}

// ---------------- layer-0 aggregation ---------------------------------------
__global__ void __launch_bounds__(256) agg0_kernel(const int* __restrict__ z) {
    __shared__ float bins[8][128];
    int w = threadIdx.x >> 5, lane = threadIdx.x & 31;
    int n = blockIdx.x * 8 + w;
    ((float4*)bins[w])[lane] = make_float4(0.f, 0.f, 0.f, 0.f);
    __syncwarp();
    int s = g_offs[n], e = g_offs[n + 1];
    for (int j = s + lane; j < e; j += 32) {
        int r = g_csr[j];
        atomicAdd(&bins[w][z[r]], g_dis[r]);
    }
    __syncwarp();
    if (lane == 0) bins[w][z[n]] += g_dis[n];
    __syncwarp();
    float dc = g_dis[n];
    float4 b = ((float4*)bins[w])[lane];
    b.x *= dc; b.y *= dc; b.z *= dc; b.w *= dc;
    ((float4*)(g_Agg + (size_t)n * HID))[lane] = b;
}

// ---------------- layers 1/2: CSR gather ------------------------------------
__global__ void __launch_bounds__(256) gather_kernel() {
    int gt = blockIdx.x * blockDim.x + threadIdx.x;
    int n = gt >> 5, lane = gt & 31;
    const float4* Y4 = (const float4*)g_Y;
    float4 acc = Y4[(size_t)n * 32 + lane];
    float4 acc2 = make_float4(0.f, 0.f, 0.f, 0.f);
    int s = g_offs[n], e = g_offs[n + 1];
    int j = s;
    for (; j + 2 <= e; j += 2) {
        int r0 = g_csr[j], r1 = g_csr[j + 1];
        float4 v0 = Y4[(size_t)r0 * 32 + lane];
        float4 v1 = Y4[(size_t)r1 * 32 + lane];
        acc.x += v0.x; acc.y += v0.y; acc.z += v0.z; acc.w += v0.w;
        acc2.x += v1.x; acc2.y += v1.y; acc2.z += v1.z; acc2.w += v1.w;
    }
    if (j < e) {
        int r = g_csr[j];
        float4 v = Y4[(size_t)r * 32 + lane];
        acc.x += v.x; acc.y += v.y; acc.z += v.z; acc.w += v.w;
    }
    acc.x += acc2.x; acc.y += acc2.y; acc.z += acc2.z; acc.w += acc2.w;
    float dc = g_dis[n];
    acc.x *= dc; acc.y *= dc; acc.z *= dc; acc.w *= dc;
    ((float4*)(g_Agg))[(size_t)n * 32 + lane] = acc;
}

// ---------------- GEMM v5: 64x128 tile, 128 thr, 8x8, conflict-free W -------
// A row-major padded in smem (broadcast scalar reads, 2 addrs/warp).
// W staged per kc as pair-permuted ull: Wp[kk][p][tx] = (W[k][32p+tx], W[k][32p+tx+16])
// -> inner LDS.64 at 8-byte lane stride = conflict-free.
// Thread (tx,ty): rows ty*8..+7, col pairs (tx+32p, tx+32p+16), p=0..3.
#define AROWS 132
__global__ void __launch_bounds__(128, 4) gemm_tanh_kernel(const float* __restrict__ W,
                                                           const float* __restrict__ bias,
                                                           int out_off, int writeY) {
    __shared__ float As[64 * AROWS];
    __shared__ unsigned long long Wp[16 * 4 * 16];   // [kk][p][tx]
    int t = threadIdx.x;
    int rbase = blockIdx.x * 64;
    int tx = t & 15, ty = t >> 4;
    int row0 = ty * 8;

    // stage A row-major (coalesced, padded stride)
    {
        const float4* A4 = (const float4*)(g_Agg + (size_t)rbase * HID);
        #pragma unroll
        for (int i = 0; i < 16; ++i) {
            int idx = t + i * 128;
            int r = idx >> 5, c4 = idx & 31;
            *(float4*)(As + r * AROWS + c4 * 4) = A4[idx];
        }
    }

    unsigned long long acc[8][4];
    #pragma unroll
    for (int i = 0; i < 8; ++i)
        #pragma unroll
        for (int p = 0; p < 4; ++p) acc[i][p] = 0ull;

    for (int kc = 0; kc < 8; ++kc) {
        __syncthreads();                                  // covers A staging on kc==0
        // stage pair-permuted W for these 16 k rows
        {
            const float* Wk = W + kc * 16 * 128;
            #pragma unroll
            for (int i = 0; i < 8; ++i) {
                int idx = t + i * 128;                    // 0..1023
                int kk = idx >> 6, rem = idx & 63;
                int p = rem >> 4, txc = rem & 15;
                float lo = Wk[kk * 128 + 32 * p + txc];
                float hi = Wk[kk * 128 + 32 * p + txc + 16];
                unsigned long long pr;
                PACKF2(pr, lo, hi);
                Wp[idx] = pr;
            }
        }
        __syncthreads();
        #pragma unroll
        for (int kk = 0; kk < 16; ++kk) {
            int k = kc * 16 + kk;
            unsigned long long ad[8];
            #pragma unroll
            for (int i = 0; i < 8; ++i) {
                float a = As[(row0 + i) * AROWS + k];
                PACKF2(ad[i], a, a);
            }
            unsigned long long w0 = Wp[(kk * 4 + 0) * 16 + tx];
            unsigned long long w1 = Wp[(kk * 4 + 1) * 16 + tx];
            unsigned long long w2 = Wp[(kk * 4 + 2) * 16 + tx];
            unsigned long long w3 = Wp[(kk * 4 + 3) * 16 + tx];
            #pragma unroll
            for (int i = 0; i < 8; ++i) {
                FMAF2(acc[i][0], ad[i], w0);
                FMAF2(acc[i][1], ad[i], w1);
                FMAF2(acc[i][2], ad[i], w2);
                FMAF2(acc[i][3], ad[i], w3);
            }
        }
    }

    float blo[4], bhi[4];
    #pragma unroll
    for (int p = 0; p < 4; ++p) {
        blo[p] = __ldg(&bias[tx + 32 * p]);
        bhi[p] = __ldg(&bias[tx + 32 * p + 16]);
    }

    #pragma unroll
    for (int i = 0; i < 8; ++i) {
        int rown = rbase + row0 + i;
        float dr = g_dis[rown];
        float* o = g_X + (size_t)rown * DD + out_off;
        float* y = g_Y + (size_t)rown * HID;
        #pragma unroll
        for (int p = 0; p < 4; ++p) {
            float lo, hi;
            UNPACKF2(lo, hi, acc[i][p]);
            float vlo = tanhf(lo + blo[p]);
            float vhi = tanhf(hi + bhi[p]);
            int clo = tx + 32 * p, chi = clo + 16;
            o[clo] = vlo;
            o[chi] = vhi;
            if (writeY) { y[clo] = vlo * dr; y[chi] = vhi * dr; }
        }
    }
}

// ---------------- per-graph head --------------------------------------------
__global__ void __launch_bounds__(256) head_kernel(
        const float* __restrict__ Wc1, const float* __restrict__ bc1,
        const float* __restrict__ Wc2, const float* __restrict__ bc2,
        const float* __restrict__ g1,  const float* __restrict__ be1,
        const float* __restrict__ g2,  const float* __restrict__ be2,
        const float* __restrict__ Wl1, const float* __restrict__ bl1,
        const float* __restrict__ Wl2, const float* __restrict__ bl2,
        const float* __restrict__ rm1, const float* __restrict__ rv1,
        const float* __restrict__ rm2, const float* __restrict__ rv2,
        float* __restrict__ out) {
    __shared__ float keys[SMAX];
    __shared__ int   topk[KK];
    __shared__ float Wc1s[C1n * DD];
    __shared__ float c1s[C1n * KK];
    __shared__ float h2s[C2n * L2n];
    __shared__ float ps[FLAT];
    __shared__ float f1[128];
    __shared__ float red[256];

    int b = blockIdx.x, tid = threadIdx.x, bd = blockDim.x;
    int M = g_bcnt[b];
    if (M > SMAX) M = SMAX;
    int s = g_starts[b];

    for (int i = tid; i < C1n * DD; i += bd) Wc1s[i] = Wc1[i];
    for (int i = tid; i < M; i += bd) keys[i] = g_X[(size_t)(s + i) * DD + (DD - 1)];
    for (int i = tid; i < KK; i += bd) topk[i] = -1;
    __syncthreads();

    for (int i = tid; i < M; i += bd) {
        float ki = keys[i];
        int r = 0;
        for (int j = 0; j < M; ++j) {
            float kj = keys[j];
            r += (kj > ki) || (kj == ki && j < i);
        }
        if (r < KK) topk[r] = s + i;
    }
    __syncthreads();

    for (int o = tid; o < C1n * KK; o += bd) {
        int c = o & 15, k = o >> 4;
        int node = topk[k];
        float acc = __ldg(&bc1[c]);
        if (node >= 0) {
            const float* xr = g_X + (size_t)node * DD;
            const float* w = Wc1s + c * DD;
            #pragma unroll 4
            for (int d = 0; d < DD; ++d) acc += xr[d] * w[d];
        }
        float v = fmaxf(acc, 0.f);
        v = (v - __ldg(&rm1[c])) * (__ldg(&g1[c]) * rsqrtf(__ldg(&rv1[c]) + EPSc)) + __ldg(&be1[c]);
        c1s[c * KK + k] = v;
    }
    __syncthreads();

    for (int o = tid; o < C2n * L2n; o += bd) {
        int oc = o / L2n, tt = o % L2n;
        float acc = __ldg(&bc2[oc]);
        const float* w = Wc2 + oc * (C1n * KERNL);
        for (int ic = 0; ic < C1n; ++ic) {
            #pragma unroll
            for (int kk = 0; kk < KERNL; ++kk)
                acc += c1s[ic * KK + tt + kk] * __ldg(&w[ic * KERNL + kk]);
        }
        float v = fmaxf(acc, 0.f);
        v = (v - __ldg(&rm2[oc])) * (__ldg(&g2[oc]) * rsqrtf(__ldg(&rv2[oc]) + EPSc)) + __ldg(&be2[oc]);
        h2s[oc * L2n + tt] = v;
    }
    __syncthreads();

    for (int o = tid; o < FLAT; o += bd) {
        int oc = o / PL, l = o % PL;
        ps[o] = fmaxf(h2s[oc * L2n + 2 * l], h2s[oc * L2n + 2 * l + 1]);
    }
    __syncthreads();

    for (int j = tid; j < 128; j += bd) {
        float acc = __ldg(&bl1[j]);
        const float* w = Wl1 + j * FLAT;
        #pragma unroll 4
        for (int i = 0; i < FLAT; ++i) acc += ps[i] * __ldg(&w[i]);
        f1[j] = fmaxf(acc, 0.f);
    }
    __syncthreads();

    float p = 0.f;
    if (tid < 128) p = f1[tid] * __ldg(&Wl2[tid]);
    red[tid] = p;
    __syncthreads();
    for (int off = 128; off > 0; off >>= 1) {
        if (tid < off && tid + off < bd) red[tid] += red[tid + off];
        __syncthreads();
    }
    if (tid == 0) out[b] = red[0] + __ldg(&bl2[0]);
}

// ---------------- host orchestration ----------------------------------------
extern "C" void kernel_launch(void* const* d_in, const int* in_sizes, int n_in,
                              void* d_out, int out_size) {
    const int*   z     = (const int*)d_in[0];
    const int*   ei    = (const int*)d_in[1];
    const int*   batch = (const int*)d_in[2];
    const float* W0    = (const float*)d_in[3];
    const float* b0    = (const float*)d_in[4];
    const float* W1    = (const float*)d_in[5];
    const float* b1    = (const float*)d_in[6];
    const float* W2    = (const float*)d_in[7];
    const float* b2    = (const float*)d_in[8];
    const float* Wc1   = (const float*)d_in[9];
    const float* bc1   = (const float*)d_in[10];
    const float* Wc2   = (const float*)d_in[11];
    const float* bc2   = (const float*)d_in[12];
    const float* g1    = (const float*)d_in[13];
    const float* be1   = (const float*)d_in[14];
    const float* g2    = (const float*)d_in[15];
    const float* be2   = (const float*)d_in[16];
    const float* Wl1   = (const float*)d_in[17];
    const float* bl1   = (const float*)d_in[18];
    const float* Wl2   = (const float*)d_in[19];
    const float* bl2   = (const float*)d_in[20];
    const float* rm1   = (const float*)d_in[21];
    const float* rv1   = (const float*)d_in[22];
    const float* rm2   = (const float*)d_in[23];
    const float* rv2   = (const float*)d_in[24];
    float* out = (float*)d_out;

    const int* row = ei;
    const int* col = ei + Ee;

    init_kernel<<<(Nn + 255) / 256, 256>>>();                 // 0
    count_kernel<<<(Ee + 255) / 256, 256>>>(col, batch);      // 1
    scanA_kernel<<<SCANB, 256>>>();                           // 2
    // PROBE (profiled slot): quarter-size GEMM v5 on scratch; outputs fully
    // overwritten by the real pipeline below.
    gemm_tanh_kernel<<<512, 128>>>(W0, b0, 0, 1);             // 3  <-- profiled
    scanB_kernel<<<1, SCANB>>>();                             // 4
    scanC_kernel<<<SCANB, 256>>>();                           // 5
    scan_batch_kernel<<<1, Bb>>>();                           // 6
    fill_kernel<<<(Ee + 255) / 256, 256>>>(row, col);         // 7

    agg0_kernel<<<Nn / 8, 256>>>(z);                          // 8
    gemm_tanh_kernel<<<Nn / 64, 128>>>(W0, b0, 0, 1);         // 9

    gather_kernel<<<Nn * 32 / 256, 256>>>();                  // 10
    gemm_tanh_kernel<<<Nn / 64, 128>>>(W1, b1, HID, 1);       // 11

    gather_kernel<<<Nn * 32 / 256, 256>>>();                  // 12
    gemm_tanh_kernel<<<Nn / 64, 128>>>(W2, b2, 2 * HID, 0);   // 13

    head_kernel<<<Bb, 256>>>(Wc1, bc1, Wc2, bc2, g1, be1, g2, be2,
                             Wl1, bl1, Wl2, bl2, rm1, rv1, rm2, rv2, out);  // 14
}